// round 1
// baseline (speedup 1.0000x reference)
#include <cuda_runtime.h>
#include <math.h>

#define SEQ 4096
#define HID 1280
#define NH 16
#define HD 80
#define HALF 40

// ---------------- scratch (device globals: no allocation allowed) ----------
__device__ float g_qkv[(size_t)SEQ * 3 * HID];   // 62.9 MB
__device__ float g_q[(size_t)NH * SEQ * HD];     // 21 MB (RoPE'd, head-major)
__device__ float g_k[(size_t)NH * SEQ * HD];
__device__ float g_v[(size_t)NH * SEQ * HD];
__device__ float g_attn[(size_t)SEQ * HID];      // attention output, seq-major

// ---------------- GEMM: C[M,N] = A[M,K] @ B[N,K]^T + bias ------------------
// Both A and B are K-contiguous. 128x128 block tile, BK=16, 256 threads,
// 8x8 per-thread micro-tile (two 4-wide float4 fragments per operand).
#define GBM 128
#define GBN 128
#define GBK 16

__global__ __launch_bounds__(256) void gemm_bias_kernel(
    const float* __restrict__ A, const float* __restrict__ B,
    const float* __restrict__ bias, float* __restrict__ C,
    int M, int N, int K)
{
    __shared__ float As[GBK][GBM + 4];
    __shared__ float Bs[GBK][GBN + 4];
    const int bm = blockIdx.y * GBM;
    const int bn = blockIdx.x * GBN;
    const int tid = threadIdx.x;
    const int tx = tid & 15;
    const int ty = tid >> 4;

    float acc[8][8];
    #pragma unroll
    for (int i = 0; i < 8; i++)
        #pragma unroll
        for (int j = 0; j < 8; j++) acc[i][j] = 0.f;

    const int lrow = tid >> 2;          // 0..63
    const int lcol = (tid & 3) << 2;    // 0,4,8,12

    for (int k0 = 0; k0 < K; k0 += GBK) {
        #pragma unroll
        for (int i = 0; i < 2; i++) {
            int row = lrow + i * 64;
            float4 av = *(const float4*)(A + (size_t)(bm + row) * K + k0 + lcol);
            As[lcol + 0][row] = av.x; As[lcol + 1][row] = av.y;
            As[lcol + 2][row] = av.z; As[lcol + 3][row] = av.w;
            float4 bv = *(const float4*)(B + (size_t)(bn + row) * K + k0 + lcol);
            Bs[lcol + 0][row] = bv.x; Bs[lcol + 1][row] = bv.y;
            Bs[lcol + 2][row] = bv.z; Bs[lcol + 3][row] = bv.w;
        }
        __syncthreads();
        #pragma unroll
        for (int k = 0; k < GBK; k++) {
            float a[8], b[8];
            *(float4*)&a[0] = *(const float4*)&As[k][ty * 4];
            *(float4*)&a[4] = *(const float4*)&As[k][64 + ty * 4];
            *(float4*)&b[0] = *(const float4*)&Bs[k][tx * 4];
            *(float4*)&b[4] = *(const float4*)&Bs[k][64 + tx * 4];
            #pragma unroll
            for (int i = 0; i < 8; i++)
                #pragma unroll
                for (int j = 0; j < 8; j++)
                    acc[i][j] += a[i] * b[j];
        }
        __syncthreads();
    }
    #pragma unroll
    for (int ih = 0; ih < 2; ih++)
        #pragma unroll
        for (int i = 0; i < 4; i++) {
            int row = bm + ih * 64 + ty * 4 + i;
            #pragma unroll
            for (int jh = 0; jh < 2; jh++) {
                int col = bn + jh * 64 + tx * 4;
                float4 bv = *(const float4*)(bias + col);
                float4 o;
                o.x = acc[ih * 4 + i][jh * 4 + 0] + bv.x;
                o.y = acc[ih * 4 + i][jh * 4 + 1] + bv.y;
                o.z = acc[ih * 4 + i][jh * 4 + 2] + bv.z;
                o.w = acc[ih * 4 + i][jh * 4 + 3] + bv.w;
                *(float4*)(C + (size_t)row * N + col) = o;
            }
        }
}

// ---------------- RoPE + split into head-major Q/K/V -----------------------
__global__ __launch_bounds__(256) void rope_kernel(
    const float* __restrict__ cosp, const float* __restrict__ sinp)
{
    int idx = blockIdx.x * blockDim.x + threadIdx.x;
    if (idx >= SEQ * NH * HD) return;
    int d = idx % HD;
    int h = (idx / HD) % NH;
    int s = idx / (HD * NH);
    float c = cosp[s * HD + d], sn = sinp[s * HD + d];
    const float* base = g_qkv + (size_t)s * 3 * HID + h * HD;
    float qv = base[d];
    float kv = base[HID + d];
    float vv = base[2 * HID + d];
    float qr = (d < HALF) ? -base[d + HALF] : base[d - HALF];
    float kr = (d < HALF) ? -base[HID + d + HALF] : base[HID + d - HALF];
    size_t o = (size_t)h * SEQ * HD + (size_t)s * HD + d;
    g_q[o] = qv * c + qr * sn;
    g_k[o] = kv * c + kr * sn;
    g_v[o] = vv;
}

// ---------------- Flash-style attention ------------------------------------
// Block: 128 query rows x one head. Key loop over 128-wide tiles of the
// segment range. S = Q K^T computed as 8x8-microtile GEMM on transposed smem
// tiles. Online softmax stats (m, l, tile-factor) per row in smem. PV with
// 4 rows x 10 dims register blocking per thread.
#define ABM 128
#define ABN 128
#define TSTR 132          // padded stride for Qt/Kt rows ([HD][128+4])
#define SMSTR 129         // padded stride for probability tile

#define ATTN_SMEM_FLOATS (2 * HD * TSTR + ABN * HD + ABM * SMSTR + 3 * ABM)
#define ATTN_SMEM_BYTES  (ATTN_SMEM_FLOATS * 4)

__global__ __launch_bounds__(256) void attn_kernel(
    const float* __restrict__ Q, const float* __restrict__ K,
    const float* __restrict__ V, const int* __restrict__ cu,
    int nseg, float* __restrict__ Out)
{
    extern __shared__ float sm[];
    float* Qt   = sm;                        // [HD][TSTR]
    float* Kt   = Qt + HD * TSTR;            // [HD][TSTR]
    float* Vs   = Kt + HD * TSTR;            // [ABN][HD]
    float* Sm   = Vs + ABN * HD;             // [ABM][SMSTR]
    float* rowm = Sm + ABM * SMSTR;          // [ABM]
    float* rowl = rowm + ABM;
    float* rowf = rowl + ABM;
    __shared__ int cus[16];

    const int tid = threadIdx.x;
    const int h   = blockIdx.y;
    const int r0  = blockIdx.x * ABM;
    const float scale = rsqrtf((float)HD);

    const int tx = tid & 15;
    const int ty = tid >> 4;

    if (tid <= nseg) cus[tid] = cu[tid];
    if (tid < ABM) { rowm[tid] = -INFINITY; rowl[tid] = 0.f; }

    const float* Qg = Q + (size_t)h * SEQ * HD + (size_t)r0 * HD;
    const float* Kg = K + (size_t)h * SEQ * HD;
    const float* Vg = V + (size_t)h * SEQ * HD;

    for (int idx = tid; idx < ABM * HD; idx += 256) {
        int r = idx / HD, d = idx % HD;
        Qt[d * TSTR + r] = Qg[idx];
    }
    __syncthreads();

    // per-thread S-phase row segment bounds
    int rst[8], ren[8];
    #pragma unroll
    for (int ih = 0; ih < 2; ih++)
        #pragma unroll
        for (int i = 0; i < 4; i++) {
            int r = r0 + ih * 64 + ty * 4 + i;
            int st = 0, en = SEQ;
            for (int t = 0; t < nseg; t++)
                if (r >= cus[t]) { st = cus[t]; en = cus[t + 1]; }
            rst[ih * 4 + i] = st; ren[ih * 4 + i] = en;
        }

    // block-wide key range
    int blk_start = 0, blk_end = SEQ;
    for (int t = 0; t < nseg; t++) {
        if (r0 >= cus[t]) blk_start = cus[t];
        if (r0 + ABM - 1 >= cus[t]) blk_end = cus[t + 1];
    }
    int kb0 = (blk_start / ABN) * ABN;

    // O accumulators: 4 rows x 10 dims per thread
    const int orow0 = (tid >> 3) * 4;      // 0..124
    const int d0    = (tid & 7) * 10;      // 0..70
    float oacc[4][10];
    #pragma unroll
    for (int r = 0; r < 4; r++)
        #pragma unroll
        for (int d = 0; d < 10; d++) oacc[r][d] = 0.f;

    for (int kb = kb0; kb < blk_end; kb += ABN) {
        // load K (transposed) and V tiles
        for (int idx = tid; idx < ABN * HD; idx += 256) {
            int j = idx / HD, d = idx % HD;
            int jg = kb + j;
            float kv = (jg < SEQ) ? Kg[(size_t)jg * HD + d] : 0.f;
            float vv = (jg < SEQ) ? Vg[(size_t)jg * HD + d] : 0.f;
            Kt[d * TSTR + j] = kv;
            Vs[j * HD + d]   = vv;
        }
        __syncthreads();

        // ---- S = Q K^T (8x8 micro-tile per thread) ----
        float sacc[8][8];
        #pragma unroll
        for (int i = 0; i < 8; i++)
            #pragma unroll
            for (int j = 0; j < 8; j++) sacc[i][j] = 0.f;

        #pragma unroll 4
        for (int d = 0; d < HD; d++) {
            float a[8], b[8];
            *(float4*)&a[0] = *(const float4*)&Qt[d * TSTR + ty * 4];
            *(float4*)&a[4] = *(const float4*)&Qt[d * TSTR + 64 + ty * 4];
            *(float4*)&b[0] = *(const float4*)&Kt[d * TSTR + tx * 4];
            *(float4*)&b[4] = *(const float4*)&Kt[d * TSTR + 64 + tx * 4];
            #pragma unroll
            for (int i = 0; i < 8; i++)
                #pragma unroll
                for (int j = 0; j < 8; j++)
                    sacc[i][j] += a[i] * b[j];
        }

        // ---- mask + online softmax (16 lanes per row) ----
        #pragma unroll
        for (int ih = 0; ih < 2; ih++)
            #pragma unroll
            for (int i = 0; i < 4; i++) {
                const int i8 = ih * 4 + i;
                const int r  = ih * 64 + ty * 4 + i;
                const int st = rst[i8], en = ren[i8];
                float tm = -INFINITY;
                #pragma unroll
                for (int jh = 0; jh < 2; jh++)
                    #pragma unroll
                    for (int j = 0; j < 4; j++) {
                        int col = kb + jh * 64 + tx * 4 + j;
                        float s = sacc[i8][jh * 4 + j] * scale;
                        if (col < st || col >= en) s = -INFINITY;
                        sacc[i8][jh * 4 + j] = s;
                        tm = fmaxf(tm, s);
                    }
                // row-max over the 16 lanes sharing this row
                #pragma unroll
                for (int w = 1; w < 16; w <<= 1)
                    tm = fmaxf(tm, __shfl_xor_sync(0xffffffffu, tm, w, 16));
                float mo = rowm[r];
                float mn = fmaxf(mo, tm);
                bool dead = (mn == -INFINITY);
                float sum = 0.f;
                #pragma unroll
                for (int jh = 0; jh < 2; jh++)
                    #pragma unroll
                    for (int j = 0; j < 4; j++) {
                        float p = dead ? 0.f : __expf(sacc[i8][jh * 4 + j] - mn);
                        Sm[r * SMSTR + jh * 64 + tx * 4 + j] = p;
                        sum += p;
                    }
                #pragma unroll
                for (int w = 1; w < 16; w <<= 1)
                    sum += __shfl_xor_sync(0xffffffffu, sum, w, 16);
                if (tx == 0) {
                    float f = dead ? 1.f : __expf(mo - mn);
                    rowf[r] = f;
                    rowm[r] = mn;
                    rowl[r] = rowl[r] * f + sum;
                }
            }
        __syncthreads();

        // ---- O += P V ----
        float f0 = rowf[orow0 + 0], f1 = rowf[orow0 + 1];
        float f2 = rowf[orow0 + 2], f3 = rowf[orow0 + 3];
        #pragma unroll
        for (int d = 0; d < 10; d++) {
            oacc[0][d] *= f0; oacc[1][d] *= f1;
            oacc[2][d] *= f2; oacc[3][d] *= f3;
        }
        #pragma unroll 2
        for (int j = 0; j < ABN; j++) {
            float p0 = Sm[(orow0 + 0) * SMSTR + j];
            float p1 = Sm[(orow0 + 1) * SMSTR + j];
            float p2 = Sm[(orow0 + 2) * SMSTR + j];
            float p3 = Sm[(orow0 + 3) * SMSTR + j];
            #pragma unroll
            for (int d = 0; d < 10; d++) {
                float v = Vs[j * HD + d0 + d];
                oacc[0][d] += p0 * v;
                oacc[1][d] += p1 * v;
                oacc[2][d] += p2 * v;
                oacc[3][d] += p3 * v;
            }
        }
        __syncthreads();
    }

    // ---- finalize ----
    #pragma unroll
    for (int rr = 0; rr < 4; rr++) {
        int r = orow0 + rr;
        float inv = 1.f / rowl[r];
        #pragma unroll
        for (int d = 0; d < 10; d++)
            Out[(size_t)(r0 + r) * HID + h * HD + d0 + d] = oacc[rr][d] * inv;
    }
}

// ---------------- launch ----------------------------------------------------
extern "C" void kernel_launch(void* const* d_in, const int* in_sizes, int n_in,
                              void* d_out, int out_size)
{
    const float* hidden = (const float*)d_in[0];
    const float* cosp   = (const float*)d_in[1];
    const float* sinp   = (const float*)d_in[2];
    const float* qkv_w  = (const float*)d_in[3];
    const float* qkv_b  = (const float*)d_in[4];
    const float* proj_w = (const float*)d_in[5];
    const float* proj_b = (const float*)d_in[6];
    const int*   cu     = (const int*)d_in[7];
    const int    nseg   = in_sizes[7] - 1;
    float* out = (float*)d_out;

    float *qkv, *qp, *kp, *vp, *attn;
    cudaGetSymbolAddress((void**)&qkv,  g_qkv);
    cudaGetSymbolAddress((void**)&qp,   g_q);
    cudaGetSymbolAddress((void**)&kp,   g_k);
    cudaGetSymbolAddress((void**)&vp,   g_v);
    cudaGetSymbolAddress((void**)&attn, g_attn);

    // 1) QKV GEMM: [4096,3840] = hidden @ qkv_w^T + qkv_b
    {
        dim3 grid((3 * HID) / GBN, SEQ / GBM);
        gemm_bias_kernel<<<grid, 256>>>(hidden, qkv_w, qkv_b, qkv,
                                        SEQ, 3 * HID, HID);
    }
    // 2) RoPE + head-major split
    {
        int total = SEQ * NH * HD;
        rope_kernel<<<(total + 255) / 256, 256>>>(cosp, sinp);
    }
    // 3) Attention
    {
        cudaFuncSetAttribute(attn_kernel,
                             cudaFuncAttributeMaxDynamicSharedMemorySize,
                             ATTN_SMEM_BYTES);
        dim3 grid(SEQ / ABM, NH);
        attn_kernel<<<grid, 256, ATTN_SMEM_BYTES>>>(qp, kp, vp, cu, nseg, attn);
    }
    // 4) Output projection: out = attn @ proj_w^T + proj_b
    {
        dim3 grid(HID / GBN, SEQ / GBM);
        gemm_bias_kernel<<<grid, 256>>>(attn, proj_w, proj_b, out,
                                        SEQ, HID, HID);
    }
}

// round 4
// speedup vs baseline: 1.3565x; 1.3565x over previous
#include <cuda_runtime.h>
#include <cuda_bf16.h>
#include <stdint.h>
#include <math.h>

#define SEQ 4096
#define HID 1280
#define NH 16
#define HD 80
#define HALF 40

// ---------------- scratch (device globals: no allocation allowed) ----------
__device__ float g_qkv[(size_t)SEQ * 3 * HID];
__device__ float g_q[(size_t)NH * SEQ * HD];
__device__ float g_k[(size_t)NH * SEQ * HD];
__device__ float g_v[(size_t)NH * SEQ * HD];
__device__ float g_attn[(size_t)SEQ * HID];

__device__ __nv_bfloat16 g_hh[(size_t)SEQ * HID];
__device__ __nv_bfloat16 g_hl[(size_t)SEQ * HID];
__device__ __nv_bfloat16 g_wh[(size_t)3 * HID * HID];
__device__ __nv_bfloat16 g_wl[(size_t)3 * HID * HID];
__device__ __nv_bfloat16 g_ah[(size_t)SEQ * HID];
__device__ __nv_bfloat16 g_al[(size_t)SEQ * HID];
__device__ __nv_bfloat16 g_ph[(size_t)HID * HID];
__device__ __nv_bfloat16 g_pl[(size_t)HID * HID];

// ---------------- PTX helpers ----------------------------------------------
__device__ __forceinline__ uint32_t smem_u32(const void* p) {
    uint32_t a;
    asm("{ .reg .u64 t; cvta.to.shared.u64 t, %1; cvt.u32.u64 %0, t; }"
        : "=r"(a) : "l"(p));
    return a;
}

__device__ __forceinline__ void ldsm4(uint32_t* r, uint32_t addr) {
    asm volatile("ldmatrix.sync.aligned.m8n8.x4.shared.b16 {%0,%1,%2,%3}, [%4];\n"
        : "=r"(r[0]), "=r"(r[1]), "=r"(r[2]), "=r"(r[3]) : "r"(addr));
}

__device__ __forceinline__ void mma16816(float* d, const uint32_t* a,
                                         const uint32_t* b) {
    asm volatile(
        "mma.sync.aligned.m16n8k16.row.col.f32.bf16.bf16.f32 "
        "{%0,%1,%2,%3}, {%4,%5,%6,%7}, {%8,%9}, {%0,%1,%2,%3};\n"
        : "+f"(d[0]), "+f"(d[1]), "+f"(d[2]), "+f"(d[3])
        : "r"(a[0]), "r"(a[1]), "r"(a[2]), "r"(a[3]), "r"(b[0]), "r"(b[1]));
}

__device__ __forceinline__ void cp16(uint32_t s, const void* g) {
    asm volatile("cp.async.cg.shared.global [%0], [%1], 16;\n" :: "r"(s), "l"(g));
}

// ---------------- fp32 -> (hi, lo) bf16 split -------------------------------
__global__ __launch_bounds__(256) void split_kernel(
    const float* __restrict__ src, __nv_bfloat16* __restrict__ hi,
    __nv_bfloat16* __restrict__ lo, int n)
{
    int i = blockIdx.x * blockDim.x + threadIdx.x;
    if (i >= n) return;
    float x = src[i];
    __nv_bfloat16 h = __float2bfloat16(x);
    hi[i] = h;
    lo[i] = __float2bfloat16(x - __bfloat162float(h));
}

// ---------------- HMMA split-bf16 GEMM --------------------------------------
// C[M,N] = A[M,K] @ B[N,K]^T + bias via Ah*Bh + Ah*Bl + Al*Bh, fp32 acc.
// 128x128 CTA tile, 8 warps (64x32 each), BK=64, cp.async double buffer.
#define BK 64
#define ASTR 72                       // bf16 elements per smem row (144B)
#define TILE_B (128 * ASTR * 2)       // 18432 bytes per tile
#define STAGE_B (4 * TILE_B)          // Ah,Al,Bh,Bl = 73728 bytes
#define HMMA_SMEM (2 * STAGE_B)       // 147456 bytes

__device__ __forceinline__ void gemm_prefetch(
    uint32_t sstage,
    const __nv_bfloat16* __restrict__ Agh, const __nv_bfloat16* __restrict__ Agl,
    const __nv_bfloat16* __restrict__ Bgh, const __nv_bfloat16* __restrict__ Bgl,
    int k0, int K, int tid)
{
    #pragma unroll
    for (int it = 0; it < 4; it++) {
        int idx = tid + it * 256;
        int r = idx >> 3, c8 = (idx & 7) << 3;
        uint32_t soff = (uint32_t)(r * ASTR + c8) * 2;
        size_t ga = (size_t)r * K + k0 + c8;
        cp16(sstage + soff,               Agh + ga);
        cp16(sstage + TILE_B + soff,      Agl + ga);
        cp16(sstage + 2 * TILE_B + soff,  Bgh + ga);
        cp16(sstage + 3 * TILE_B + soff,  Bgl + ga);
    }
}

__global__ __launch_bounds__(256, 1) void hmma_gemm_kernel(
    const __nv_bfloat16* __restrict__ Ah, const __nv_bfloat16* __restrict__ Al,
    const __nv_bfloat16* __restrict__ Bh, const __nv_bfloat16* __restrict__ Bl,
    const float* __restrict__ bias, float* __restrict__ C, int N, int K)
{
    extern __shared__ char smraw[];
    const uint32_t sb = smem_u32(smraw);
    const int tid = threadIdx.x;
    const int wid = tid >> 5, lane = tid & 31;
    const int wm = (wid >> 2) * 64;       // warp M offset within CTA tile
    const int wn = (wid & 3) * 32;        // warp N offset
    const int bm = blockIdx.y * 128, bn = blockIdx.x * 128;

    const int lg = lane >> 3, lr = lane & 7;
    const int a_r = lr + ((lg & 1) << 3), a_c = (lg >> 1) << 3;
    const int b_r = lr + ((lg >> 1) << 3), b_c = (lg & 1) << 3;

    const __nv_bfloat16* Agh = Ah + (size_t)bm * K;
    const __nv_bfloat16* Agl = Al + (size_t)bm * K;
    const __nv_bfloat16* Bgh = Bh + (size_t)bn * K;
    const __nv_bfloat16* Bgl = Bl + (size_t)bn * K;

    float acc[4][4][4];
    #pragma unroll
    for (int i = 0; i < 4; i++)
        #pragma unroll
        for (int j = 0; j < 4; j++)
            #pragma unroll
            for (int t = 0; t < 4; t++) acc[i][j][t] = 0.f;

    const int nc = K / BK;
    gemm_prefetch(sb, Agh, Agl, Bgh, Bgl, 0, K, tid);
    asm volatile("cp.async.commit_group;\n" ::: "memory");

    for (int c = 0; c < nc; c++) {
        if (c + 1 < nc) {
            gemm_prefetch(sb + ((c + 1) & 1) * STAGE_B, Agh, Agl, Bgh, Bgl,
                          (c + 1) * BK, K, tid);
            asm volatile("cp.async.commit_group;\n" ::: "memory");
            asm volatile("cp.async.wait_group 1;\n" ::: "memory");
        } else {
            asm volatile("cp.async.wait_group 0;\n" ::: "memory");
        }
        __syncthreads();

        const uint32_t s0 = sb + (c & 1) * STAGE_B;
        const uint32_t aH = s0, aL = s0 + TILE_B;
        const uint32_t bH = s0 + 2 * TILE_B, bL = s0 + 3 * TILE_B;

        #pragma unroll
        for (int ks = 0; ks < 4; ks++) {
            const int k = ks * 16;
            uint32_t ahf[4][4], alf[4][4], bhf[2][4], blf[2][4];
            #pragma unroll
            for (int i = 0; i < 4; i++) {
                uint32_t off = (uint32_t)((wm + i * 16 + a_r) * ASTR + k + a_c) * 2;
                ldsm4(ahf[i], aH + off);
                ldsm4(alf[i], aL + off);
            }
            #pragma unroll
            for (int p = 0; p < 2; p++) {
                uint32_t off = (uint32_t)((wn + p * 16 + b_r) * ASTR + k + b_c) * 2;
                ldsm4(bhf[p], bH + off);
                ldsm4(blf[p], bL + off);
            }
            #pragma unroll
            for (int i = 0; i < 4; i++)
                #pragma unroll
                for (int j = 0; j < 4; j++) {
                    const uint32_t* bhp = &bhf[j >> 1][(j & 1) * 2];
                    const uint32_t* blp = &blf[j >> 1][(j & 1) * 2];
                    mma16816(acc[i][j], ahf[i], bhp);
                    mma16816(acc[i][j], ahf[i], blp);
                    mma16816(acc[i][j], alf[i], bhp);
                }
        }
        __syncthreads();
    }

    // epilogue: write C + bias
    #pragma unroll
    for (int i = 0; i < 4; i++) {
        int r0 = bm + wm + i * 16 + (lane >> 2);
        #pragma unroll
        for (int j = 0; j < 4; j++) {
            int c0 = bn + wn + j * 8 + ((lane & 3) << 1);
            float b0 = __ldg(bias + c0), b1 = __ldg(bias + c0 + 1);
            *(float2*)(C + (size_t)r0 * N + c0) =
                make_float2(acc[i][j][0] + b0, acc[i][j][1] + b1);
            *(float2*)(C + (size_t)(r0 + 8) * N + c0) =
                make_float2(acc[i][j][2] + b0, acc[i][j][3] + b1);
        }
    }
}

// ---------------- RoPE + split into head-major Q/K/V -----------------------
__global__ __launch_bounds__(256) void rope_kernel(
    const float* __restrict__ cosp, const float* __restrict__ sinp)
{
    int idx = blockIdx.x * blockDim.x + threadIdx.x;
    if (idx >= SEQ * NH * HD) return;
    int d = idx % HD;
    int h = (idx / HD) % NH;
    int s = idx / (HD * NH);
    float c = cosp[s * HD + d], sn = sinp[s * HD + d];
    const float* base = g_qkv + (size_t)s * 3 * HID + h * HD;
    float qv = base[d];
    float kv = base[HID + d];
    float vv = base[2 * HID + d];
    float qr = (d < HALF) ? -base[d + HALF] : base[d - HALF];
    float kr = (d < HALF) ? -base[HID + d + HALF] : base[HID + d - HALF];
    size_t o = (size_t)h * SEQ * HD + (size_t)s * HD + d;
    g_q[o] = qv * c + qr * sn;
    g_k[o] = kv * c + kr * sn;
    g_v[o] = vv;
}

// ---------------- Flash-style attention (fp32 SIMT) ------------------------
#define ABM 128
#define ABN 128
#define TSTR 132
#define SMSTR 129
#define ATTN_SMEM_FLOATS (2 * HD * TSTR + ABN * HD + ABM * SMSTR + 3 * ABM)
#define ATTN_SMEM_BYTES  (ATTN_SMEM_FLOATS * 4)

__global__ __launch_bounds__(256) void attn_kernel(
    const float* __restrict__ Q, const float* __restrict__ K,
    const float* __restrict__ V, const int* __restrict__ cu,
    int nseg, float* __restrict__ Out)
{
    extern __shared__ float sm[];
    float* Qt   = sm;
    float* Kt   = Qt + HD * TSTR;
    float* Vs   = Kt + HD * TSTR;
    float* Sm   = Vs + ABN * HD;
    float* rowm = Sm + ABM * SMSTR;
    float* rowl = rowm + ABM;
    float* rowf = rowl + ABM;
    __shared__ int cus[16];

    const int tid = threadIdx.x;
    const int h   = blockIdx.y;
    const int r0  = blockIdx.x * ABM;
    const float scale = rsqrtf((float)HD);

    const int tx = tid & 15;
    const int ty = tid >> 4;

    if (tid <= nseg) cus[tid] = cu[tid];
    if (tid < ABM) { rowm[tid] = -INFINITY; rowl[tid] = 0.f; }

    const float* Qg = Q + (size_t)h * SEQ * HD + (size_t)r0 * HD;
    const float* Kg = K + (size_t)h * SEQ * HD;
    const float* Vg = V + (size_t)h * SEQ * HD;

    for (int idx = tid; idx < ABM * HD; idx += 256) {
        int r = idx / HD, d = idx % HD;
        Qt[d * TSTR + r] = Qg[idx];
    }
    __syncthreads();

    int rst[8], ren[8];
    #pragma unroll
    for (int ih = 0; ih < 2; ih++)
        #pragma unroll
        for (int i = 0; i < 4; i++) {
            int r = r0 + ih * 64 + ty * 4 + i;
            int st = 0, en = SEQ;
            for (int t = 0; t < nseg; t++)
                if (r >= cus[t]) { st = cus[t]; en = cus[t + 1]; }
            rst[ih * 4 + i] = st; ren[ih * 4 + i] = en;
        }

    int blk_start = 0, blk_end = SEQ;
    for (int t = 0; t < nseg; t++) {
        if (r0 >= cus[t]) blk_start = cus[t];
        if (r0 + ABM - 1 >= cus[t]) blk_end = cus[t + 1];
    }
    int kb0 = (blk_start / ABN) * ABN;

    const int orow0 = (tid >> 3) * 4;
    const int d0    = (tid & 7) * 10;
    float oacc[4][10];
    #pragma unroll
    for (int r = 0; r < 4; r++)
        #pragma unroll
        for (int d = 0; d < 10; d++) oacc[r][d] = 0.f;

    for (int kb = kb0; kb < blk_end; kb += ABN) {
        for (int idx = tid; idx < ABN * HD; idx += 256) {
            int j = idx / HD, d = idx % HD;
            int jg = kb + j;
            float kv = (jg < SEQ) ? Kg[(size_t)jg * HD + d] : 0.f;
            float vv = (jg < SEQ) ? Vg[(size_t)jg * HD + d] : 0.f;
            Kt[d * TSTR + j] = kv;
            Vs[j * HD + d]   = vv;
        }
        __syncthreads();

        float sacc[8][8];
        #pragma unroll
        for (int i = 0; i < 8; i++)
            #pragma unroll
            for (int j = 0; j < 8; j++) sacc[i][j] = 0.f;

        #pragma unroll 4
        for (int d = 0; d < HD; d++) {
            float a[8], b[8];
            *(float4*)&a[0] = *(const float4*)&Qt[d * TSTR + ty * 4];
            *(float4*)&a[4] = *(const float4*)&Qt[d * TSTR + 64 + ty * 4];
            *(float4*)&b[0] = *(const float4*)&Kt[d * TSTR + tx * 4];
            *(float4*)&b[4] = *(const float4*)&Kt[d * TSTR + 64 + tx * 4];
            #pragma unroll
            for (int i = 0; i < 8; i++)
                #pragma unroll
                for (int j = 0; j < 8; j++)
                    sacc[i][j] += a[i] * b[j];
        }

        #pragma unroll
        for (int ih = 0; ih < 2; ih++)
            #pragma unroll
            for (int i = 0; i < 4; i++) {
                const int i8 = ih * 4 + i;
                const int r  = ih * 64 + ty * 4 + i;
                const int st = rst[i8], en = ren[i8];
                float tm = -INFINITY;
                #pragma unroll
                for (int jh = 0; jh < 2; jh++)
                    #pragma unroll
                    for (int j = 0; j < 4; j++) {
                        int col = kb + jh * 64 + tx * 4 + j;
                        float s = sacc[i8][jh * 4 + j] * scale;
                        if (col < st || col >= en) s = -INFINITY;
                        sacc[i8][jh * 4 + j] = s;
                        tm = fmaxf(tm, s);
                    }
                #pragma unroll
                for (int w = 1; w < 16; w <<= 1)
                    tm = fmaxf(tm, __shfl_xor_sync(0xffffffffu, tm, w, 16));
                float mo = rowm[r];
                float mn = fmaxf(mo, tm);
                bool dead = (mn == -INFINITY);
                float sum = 0.f;
                #pragma unroll
                for (int jh = 0; jh < 2; jh++)
                    #pragma unroll
                    for (int j = 0; j < 4; j++) {
                        float p = dead ? 0.f : __expf(sacc[i8][jh * 4 + j] - mn);
                        Sm[r * SMSTR + jh * 64 + tx * 4 + j] = p;
                        sum += p;
                    }
                #pragma unroll
                for (int w = 1; w < 16; w <<= 1)
                    sum += __shfl_xor_sync(0xffffffffu, sum, w, 16);
                if (tx == 0) {
                    float f = dead ? 1.f : __expf(mo - mn);
                    rowf[r] = f;
                    rowm[r] = mn;
                    rowl[r] = rowl[r] * f + sum;
                }
            }
        __syncthreads();

        float f0 = rowf[orow0 + 0], f1 = rowf[orow0 + 1];
        float f2 = rowf[orow0 + 2], f3 = rowf[orow0 + 3];
        #pragma unroll
        for (int d = 0; d < 10; d++) {
            oacc[0][d] *= f0; oacc[1][d] *= f1;
            oacc[2][d] *= f2; oacc[3][d] *= f3;
        }
        #pragma unroll 2
        for (int j = 0; j < ABN; j++) {
            float p0 = Sm[(orow0 + 0) * SMSTR + j];
            float p1 = Sm[(orow0 + 1) * SMSTR + j];
            float p2 = Sm[(orow0 + 2) * SMSTR + j];
            float p3 = Sm[(orow0 + 3) * SMSTR + j];
            #pragma unroll
            for (int d = 0; d < 10; d++) {
                float v = Vs[j * HD + d0 + d];
                oacc[0][d] += p0 * v;
                oacc[1][d] += p1 * v;
                oacc[2][d] += p2 * v;
                oacc[3][d] += p3 * v;
            }
        }
        __syncthreads();
    }

    #pragma unroll
    for (int rr = 0; rr < 4; rr++) {
        int r = orow0 + rr;
        float inv = 1.f / rowl[r];
        #pragma unroll
        for (int d = 0; d < 10; d++)
            Out[(size_t)(r0 + r) * HID + h * HD + d0 + d] = oacc[rr][d] * inv;
    }
}

// ---------------- launch ----------------------------------------------------
extern "C" void kernel_launch(void* const* d_in, const int* in_sizes, int n_in,
                              void* d_out, int out_size)
{
    const float* hidden = (const float*)d_in[0];
    const float* cosp   = (const float*)d_in[1];
    const float* sinp   = (const float*)d_in[2];
    const float* qkv_w  = (const float*)d_in[3];
    const float* qkv_b  = (const float*)d_in[4];
    const float* proj_w = (const float*)d_in[5];
    const float* proj_b = (const float*)d_in[6];
    const int*   cu     = (const int*)d_in[7];
    const int    nseg   = in_sizes[7] - 1;
    float* out = (float*)d_out;

    float *qkv, *qp, *kp, *vp, *attn;
    cudaGetSymbolAddress((void**)&qkv,  g_qkv);
    cudaGetSymbolAddress((void**)&qp,   g_q);
    cudaGetSymbolAddress((void**)&kp,   g_k);
    cudaGetSymbolAddress((void**)&vp,   g_v);
    cudaGetSymbolAddress((void**)&attn, g_attn);

    __nv_bfloat16 *hh, *hl, *wh, *wl, *ah, *al, *ph, *pl;
    cudaGetSymbolAddress((void**)&hh, g_hh);
    cudaGetSymbolAddress((void**)&hl, g_hl);
    cudaGetSymbolAddress((void**)&wh, g_wh);
    cudaGetSymbolAddress((void**)&wl, g_wl);
    cudaGetSymbolAddress((void**)&ah, g_ah);
    cudaGetSymbolAddress((void**)&al, g_al);
    cudaGetSymbolAddress((void**)&ph, g_ph);
    cudaGetSymbolAddress((void**)&pl, g_pl);

    cudaFuncSetAttribute(hmma_gemm_kernel,
                         cudaFuncAttributeMaxDynamicSharedMemorySize,
                         HMMA_SMEM);
    cudaFuncSetAttribute(attn_kernel,
                         cudaFuncAttributeMaxDynamicSharedMemorySize,
                         ATTN_SMEM_BYTES);

    // 0) split inputs/weights into hi/lo bf16
    {
        int n1 = SEQ * HID;
        split_kernel<<<(n1 + 255) / 256, 256>>>(hidden, hh, hl, n1);
        int n2 = 3 * HID * HID;
        split_kernel<<<(n2 + 255) / 256, 256>>>(qkv_w, wh, wl, n2);
        int n3 = HID * HID;
        split_kernel<<<(n3 + 255) / 256, 256>>>(proj_w, ph, pl, n3);
    }
    // 1) QKV GEMM (HMMA split-bf16)
    {
        dim3 grid((3 * HID) / 128, SEQ / 128);
        hmma_gemm_kernel<<<grid, 256, HMMA_SMEM>>>(hh, hl, wh, wl,
                                                   qkv_b, qkv, 3 * HID, HID);
    }
    // 2) RoPE + head-major split
    {
        int total = SEQ * NH * HD;
        rope_kernel<<<(total + 255) / 256, 256>>>(cosp, sinp);
    }
    // 3) Attention
    {
        dim3 grid(SEQ / ABM, NH);
        attn_kernel<<<grid, 256, ATTN_SMEM_BYTES>>>(qp, kp, vp, cu, nseg, attn);
    }
    // 4) Output projection (HMMA split-bf16)
    {
        int n1 = SEQ * HID;
        split_kernel<<<(n1 + 255) / 256, 256>>>(attn, ah, al, n1);
        dim3 grid(HID / 128, SEQ / 128);
        hmma_gemm_kernel<<<grid, 256, HMMA_SMEM>>>(ah, al, ph, pl,
                                                   proj_b, out, HID, HID);
    }
}

// round 5
// speedup vs baseline: 2.8904x; 2.1307x over previous
#include <cuda_runtime.h>
#include <cuda_bf16.h>
#include <stdint.h>
#include <math.h>

#define SEQ 4096
#define HID 1280
#define NH 16
#define HD 80
#define HALF 40

// ---------------- scratch (device globals) ----------------------------------
__device__ float g_qkv[(size_t)SEQ * 3 * HID];

__device__ __nv_bfloat16 g_hh[(size_t)SEQ * HID];
__device__ __nv_bfloat16 g_hl[(size_t)SEQ * HID];
__device__ __nv_bfloat16 g_wh[(size_t)3 * HID * HID];
__device__ __nv_bfloat16 g_wl[(size_t)3 * HID * HID];
__device__ __nv_bfloat16 g_ph[(size_t)HID * HID];
__device__ __nv_bfloat16 g_pl[(size_t)HID * HID];

// split Q/K/V, head-major [h][s][d]; Q pre-scaled by HD^-0.5
__device__ __nv_bfloat16 g_qh[(size_t)NH * SEQ * HD];
__device__ __nv_bfloat16 g_ql[(size_t)NH * SEQ * HD];
__device__ __nv_bfloat16 g_kh[(size_t)NH * SEQ * HD];
__device__ __nv_bfloat16 g_kl[(size_t)NH * SEQ * HD];
__device__ __nv_bfloat16 g_vh[(size_t)NH * SEQ * HD];
__device__ __nv_bfloat16 g_vl[(size_t)NH * SEQ * HD];

// attention output, split bf16, seq-major [s][HID]
__device__ __nv_bfloat16 g_ah[(size_t)SEQ * HID];
__device__ __nv_bfloat16 g_al[(size_t)SEQ * HID];

// ---------------- PTX helpers ----------------------------------------------
__device__ __forceinline__ uint32_t smem_u32(const void* p) {
    uint32_t a;
    asm("{ .reg .u64 t; cvta.to.shared.u64 t, %1; cvt.u32.u64 %0, t; }"
        : "=r"(a) : "l"(p));
    return a;
}

__device__ __forceinline__ void ldsm4(uint32_t* r, uint32_t addr) {
    asm volatile("ldmatrix.sync.aligned.m8n8.x4.shared.b16 {%0,%1,%2,%3}, [%4];\n"
        : "=r"(r[0]), "=r"(r[1]), "=r"(r[2]), "=r"(r[3]) : "r"(addr));
}

__device__ __forceinline__ void ldsm4t(uint32_t* r, uint32_t addr) {
    asm volatile("ldmatrix.sync.aligned.m8n8.x4.trans.shared.b16 {%0,%1,%2,%3}, [%4];\n"
        : "=r"(r[0]), "=r"(r[1]), "=r"(r[2]), "=r"(r[3]) : "r"(addr));
}

__device__ __forceinline__ void mma16816(float* d, const uint32_t* a,
                                         const uint32_t* b) {
    asm volatile(
        "mma.sync.aligned.m16n8k16.row.col.f32.bf16.bf16.f32 "
        "{%0,%1,%2,%3}, {%4,%5,%6,%7}, {%8,%9}, {%0,%1,%2,%3};\n"
        : "+f"(d[0]), "+f"(d[1]), "+f"(d[2]), "+f"(d[3])
        : "r"(a[0]), "r"(a[1]), "r"(a[2]), "r"(a[3]), "r"(b[0]), "r"(b[1]));
}

__device__ __forceinline__ void cp16(uint32_t s, const void* g) {
    asm volatile("cp.async.cg.shared.global [%0], [%1], 16;\n" :: "r"(s), "l"(g));
}

__device__ __forceinline__ void splitpack(float x0, float x1,
                                          uint32_t& ph, uint32_t& pl) {
    __nv_bfloat162 h = __floats2bfloat162_rn(x0, x1);
    float h0 = __bfloat162float(h.x), h1 = __bfloat162float(h.y);
    __nv_bfloat162 l = __floats2bfloat162_rn(x0 - h0, x1 - h1);
    ph = *(uint32_t*)&h;
    pl = *(uint32_t*)&l;
}

// ---------------- fp32 -> (hi, lo) bf16 split -------------------------------
__global__ __launch_bounds__(256) void split_kernel(
    const float* __restrict__ src, __nv_bfloat16* __restrict__ hi,
    __nv_bfloat16* __restrict__ lo, int n)
{
    int i = blockIdx.x * blockDim.x + threadIdx.x;
    if (i >= n) return;
    float x = src[i];
    __nv_bfloat16 h = __float2bfloat16(x);
    hi[i] = h;
    lo[i] = __float2bfloat16(x - __bfloat162float(h));
}

// ---------------- HMMA split-bf16 GEMM (unchanged, proven) ------------------
#define BK 64
#define ASTR 72
#define TILE_B (128 * ASTR * 2)
#define STAGE_B (4 * TILE_B)
#define HMMA_SMEM (2 * STAGE_B)

__device__ __forceinline__ void gemm_prefetch(
    uint32_t sstage,
    const __nv_bfloat16* __restrict__ Agh, const __nv_bfloat16* __restrict__ Agl,
    const __nv_bfloat16* __restrict__ Bgh, const __nv_bfloat16* __restrict__ Bgl,
    int k0, int K, int tid)
{
    #pragma unroll
    for (int it = 0; it < 4; it++) {
        int idx = tid + it * 256;
        int r = idx >> 3, c8 = (idx & 7) << 3;
        uint32_t soff = (uint32_t)(r * ASTR + c8) * 2;
        size_t ga = (size_t)r * K + k0 + c8;
        cp16(sstage + soff,               Agh + ga);
        cp16(sstage + TILE_B + soff,      Agl + ga);
        cp16(sstage + 2 * TILE_B + soff,  Bgh + ga);
        cp16(sstage + 3 * TILE_B + soff,  Bgl + ga);
    }
}

__global__ __launch_bounds__(256, 1) void hmma_gemm_kernel(
    const __nv_bfloat16* __restrict__ Ah, const __nv_bfloat16* __restrict__ Al,
    const __nv_bfloat16* __restrict__ Bh, const __nv_bfloat16* __restrict__ Bl,
    const float* __restrict__ bias, float* __restrict__ C, int N, int K)
{
    extern __shared__ char smraw[];
    const uint32_t sb = smem_u32(smraw);
    const int tid = threadIdx.x;
    const int wid = tid >> 5, lane = tid & 31;
    const int wm = (wid >> 2) * 64;
    const int wn = (wid & 3) * 32;
    const int bm = blockIdx.y * 128, bn = blockIdx.x * 128;

    const int lg = lane >> 3, lr = lane & 7;
    const int a_r = lr + ((lg & 1) << 3), a_c = (lg >> 1) << 3;
    const int b_r = lr + ((lg >> 1) << 3), b_c = (lg & 1) << 3;

    const __nv_bfloat16* Agh = Ah + (size_t)bm * K;
    const __nv_bfloat16* Agl = Al + (size_t)bm * K;
    const __nv_bfloat16* Bgh = Bh + (size_t)bn * K;
    const __nv_bfloat16* Bgl = Bl + (size_t)bn * K;

    float acc[4][4][4];
    #pragma unroll
    for (int i = 0; i < 4; i++)
        #pragma unroll
        for (int j = 0; j < 4; j++)
            #pragma unroll
            for (int t = 0; t < 4; t++) acc[i][j][t] = 0.f;

    const int nc = K / BK;
    gemm_prefetch(sb, Agh, Agl, Bgh, Bgl, 0, K, tid);
    asm volatile("cp.async.commit_group;\n" ::: "memory");

    for (int c = 0; c < nc; c++) {
        if (c + 1 < nc) {
            gemm_prefetch(sb + ((c + 1) & 1) * STAGE_B, Agh, Agl, Bgh, Bgl,
                          (c + 1) * BK, K, tid);
            asm volatile("cp.async.commit_group;\n" ::: "memory");
            asm volatile("cp.async.wait_group 1;\n" ::: "memory");
        } else {
            asm volatile("cp.async.wait_group 0;\n" ::: "memory");
        }
        __syncthreads();

        const uint32_t s0 = sb + (c & 1) * STAGE_B;
        const uint32_t aH = s0, aL = s0 + TILE_B;
        const uint32_t bH = s0 + 2 * TILE_B, bL = s0 + 3 * TILE_B;

        #pragma unroll
        for (int ks = 0; ks < 4; ks++) {
            const int k = ks * 16;
            uint32_t ahf[4][4], alf[4][4], bhf[2][4], blf[2][4];
            #pragma unroll
            for (int i = 0; i < 4; i++) {
                uint32_t off = (uint32_t)((wm + i * 16 + a_r) * ASTR + k + a_c) * 2;
                ldsm4(ahf[i], aH + off);
                ldsm4(alf[i], aL + off);
            }
            #pragma unroll
            for (int p = 0; p < 2; p++) {
                uint32_t off = (uint32_t)((wn + p * 16 + b_r) * ASTR + k + b_c) * 2;
                ldsm4(bhf[p], bH + off);
                ldsm4(blf[p], bL + off);
            }
            #pragma unroll
            for (int i = 0; i < 4; i++)
                #pragma unroll
                for (int j = 0; j < 4; j++) {
                    const uint32_t* bhp = &bhf[j >> 1][(j & 1) * 2];
                    const uint32_t* blp = &blf[j >> 1][(j & 1) * 2];
                    mma16816(acc[i][j], ahf[i], bhp);
                    mma16816(acc[i][j], ahf[i], blp);
                    mma16816(acc[i][j], alf[i], bhp);
                }
        }
        __syncthreads();
    }

    #pragma unroll
    for (int i = 0; i < 4; i++) {
        int r0 = bm + wm + i * 16 + (lane >> 2);
        #pragma unroll
        for (int j = 0; j < 4; j++) {
            int c0 = bn + wn + j * 8 + ((lane & 3) << 1);
            float b0 = __ldg(bias + c0), b1 = __ldg(bias + c0 + 1);
            *(float2*)(C + (size_t)r0 * N + c0) =
                make_float2(acc[i][j][0] + b0, acc[i][j][1] + b1);
            *(float2*)(C + (size_t)(r0 + 8) * N + c0) =
                make_float2(acc[i][j][2] + b0, acc[i][j][3] + b1);
        }
    }
}

// ---------------- RoPE + split to bf16 hi/lo, head-major --------------------
__global__ __launch_bounds__(256) void rope_split_kernel(
    const float* __restrict__ cosp, const float* __restrict__ sinp)
{
    int idx = blockIdx.x * blockDim.x + threadIdx.x;
    if (idx >= SEQ * NH * HD) return;
    int d = idx % HD;
    int h = (idx / HD) % NH;
    int s = idx / (HD * NH);
    float c = cosp[s * HD + d], sn = sinp[s * HD + d];
    const float* base = g_qkv + (size_t)s * 3 * HID + h * HD;
    float qv = base[d];
    float kv = base[HID + d];
    float vv = base[2 * HID + d];
    float qr = (d < HALF) ? -base[d + HALF] : base[d - HALF];
    float kr = (d < HALF) ? -base[HID + d + HALF] : base[HID + d - HALF];
    const float scale = rsqrtf((float)HD);
    float q = (qv * c + qr * sn) * scale;     // fold softmax scale into Q
    float k = kv * c + kr * sn;
    size_t o = (size_t)h * SEQ * HD + (size_t)s * HD + d;
    __nv_bfloat16 qh = __float2bfloat16(q);
    __nv_bfloat16 kh = __float2bfloat16(k);
    __nv_bfloat16 vh = __float2bfloat16(vv);
    g_qh[o] = qh; g_ql[o] = __float2bfloat16(q - __bfloat162float(qh));
    g_kh[o] = kh; g_kl[o] = __float2bfloat16(k - __bfloat162float(kh));
    g_vh[o] = vh; g_vl[o] = __float2bfloat16(vv - __bfloat162float(vh));
}

// ---------------- HMMA flash attention (split-bf16, fp32 acc) ---------------
// grid (SEQ/128, NH), 256 threads. Warp w owns q rows 16w..16w+15.
#define QSTR 88                       // bf16 elems per smem row (176B)
#define ATILE (128 * QSTR * 2)        // 22528 bytes
#define ATTN_SMEM (6 * ATILE)         // Qh Ql Kh Kl Vh Vl = 135168

__global__ __launch_bounds__(256, 1) void hmma_attn_kernel(
    const __nv_bfloat16* __restrict__ Qh_, const __nv_bfloat16* __restrict__ Ql_,
    const __nv_bfloat16* __restrict__ Kh_, const __nv_bfloat16* __restrict__ Kl_,
    const __nv_bfloat16* __restrict__ Vh_, const __nv_bfloat16* __restrict__ Vl_,
    const int* __restrict__ cu, int nseg,
    __nv_bfloat16* __restrict__ Oh_, __nv_bfloat16* __restrict__ Ol_)
{
    extern __shared__ char smraw[];
    const uint32_t sb = smem_u32(smraw);
    const uint32_t sQh = sb,             sQl = sb + ATILE;
    const uint32_t sKh = sb + 2 * ATILE, sKl = sb + 3 * ATILE;
    const uint32_t sVh = sb + 4 * ATILE, sVl = sb + 5 * ATILE;
    __shared__ int cus[17];

    const int tid = threadIdx.x;
    const int wid = tid >> 5, lane = tid & 31;
    const int h = blockIdx.y;
    const int r0 = blockIdx.x * 128;

    const int lg = lane >> 3, lr = lane & 7;
    const int a_r = lr + ((lg & 1) << 3), a_c = (lg >> 1) << 3;
    const int b_r = lr + ((lg >> 1) << 3), b_c = (lg & 1) << 3;

    if (tid <= nseg) cus[tid] = cu[tid];

    // load Q tile (rows r0..r0+127) hi/lo
    {
        const __nv_bfloat16* qh = Qh_ + ((size_t)h * SEQ + r0) * HD;
        const __nv_bfloat16* ql = Ql_ + ((size_t)h * SEQ + r0) * HD;
        for (int idx = tid; idx < 128 * 10; idx += 256) {
            int row = idx / 10, c8 = (idx % 10) * 8;
            uint32_t soff = (uint32_t)(row * QSTR + c8) * 2;
            cp16(sQh + soff, qh + (size_t)row * HD + c8);
            cp16(sQl + soff, ql + (size_t)row * HD + c8);
        }
        asm volatile("cp.async.commit_group;\n" ::: "memory");
    }
    __syncthreads();

    // per-thread row segment bounds (rows gr1, gr1+8)
    const int gr1 = r0 + 16 * wid + (lane >> 2);
    int st1 = 0, en1 = SEQ, st2 = 0, en2 = SEQ;
    for (int t = 0; t < nseg; t++) {
        if (gr1     >= cus[t]) { st1 = cus[t]; en1 = cus[t + 1]; }
        if (gr1 + 8 >= cus[t]) { st2 = cus[t]; en2 = cus[t + 1]; }
    }
    int blk_start = 0, blk_end = SEQ;
    for (int t = 0; t < nseg; t++) {
        if (r0 >= cus[t]) blk_start = cus[t];
        if (r0 + 127 >= cus[t]) blk_end = cus[t + 1];
    }
    const int kb0 = (blk_start / 128) * 128;

    float m1 = -INFINITY, m2 = -INFINITY, l1 = 0.f, l2 = 0.f;
    float oacc[10][4];
    #pragma unroll
    for (int j = 0; j < 10; j++)
        #pragma unroll
        for (int t = 0; t < 4; t++) oacc[j][t] = 0.f;

    const __nv_bfloat16* Kgh = Kh_ + (size_t)h * SEQ * HD;
    const __nv_bfloat16* Kgl = Kl_ + (size_t)h * SEQ * HD;
    const __nv_bfloat16* Vgh = Vh_ + (size_t)h * SEQ * HD;
    const __nv_bfloat16* Vgl = Vl_ + (size_t)h * SEQ * HD;

    for (int kb = kb0; kb < blk_end; kb += 128) {
        __syncthreads();   // previous tile's smem fully consumed
        for (int idx = tid; idx < 128 * 10; idx += 256) {
            int row = idx / 10, c8 = (idx % 10) * 8;
            uint32_t soff = (uint32_t)(row * QSTR + c8) * 2;
            size_t ga = (size_t)(kb + row) * HD + c8;
            cp16(sKh + soff, Kgh + ga);
            cp16(sKl + soff, Kgl + ga);
            cp16(sVh + soff, Vgh + ga);
            cp16(sVl + soff, Vgl + ga);
        }
        asm volatile("cp.async.commit_group;\n" ::: "memory");
        asm volatile("cp.async.wait_group 0;\n" ::: "memory");
        __syncthreads();

        // ---- S = Q K^T : 16 n8 frags, 5 k chunks, 3-term split ----
        float sc[16][4];
        #pragma unroll
        for (int j = 0; j < 16; j++)
            #pragma unroll
            for (int t = 0; t < 4; t++) sc[j][t] = 0.f;

        #pragma unroll
        for (int kc = 0; kc < 5; kc++) {
            uint32_t ah[4], al[4];
            uint32_t qoff = (uint32_t)((16 * wid + a_r) * QSTR + kc * 16 + a_c) * 2;
            ldsm4(ah, sQh + qoff);
            ldsm4(al, sQl + qoff);
            #pragma unroll
            for (int ng = 0; ng < 8; ng++) {
                uint32_t bh[4], bl[4];
                uint32_t koff = (uint32_t)((ng * 16 + b_r) * QSTR + kc * 16 + b_c) * 2;
                ldsm4(bh, sKh + koff);
                ldsm4(bl, sKl + koff);
                mma16816(sc[2 * ng],     ah, bh);
                mma16816(sc[2 * ng],     ah, bl);
                mma16816(sc[2 * ng],     al, bh);
                mma16816(sc[2 * ng + 1], ah, bh + 2);
                mma16816(sc[2 * ng + 1], ah, bl + 2);
                mma16816(sc[2 * ng + 1], al, bh + 2);
            }
        }

        // ---- mask + online softmax ----
        float tm1 = -INFINITY, tm2 = -INFINITY;
        #pragma unroll
        for (int j = 0; j < 16; j++) {
            int c0 = kb + j * 8 + ((lane & 3) << 1);
            int c1 = c0 + 1;
            if (c0 < st1 || c0 >= en1) sc[j][0] = -INFINITY;
            if (c1 < st1 || c1 >= en1) sc[j][1] = -INFINITY;
            if (c0 < st2 || c0 >= en2) sc[j][2] = -INFINITY;
            if (c1 < st2 || c1 >= en2) sc[j][3] = -INFINITY;
            tm1 = fmaxf(tm1, fmaxf(sc[j][0], sc[j][1]));
            tm2 = fmaxf(tm2, fmaxf(sc[j][2], sc[j][3]));
        }
        tm1 = fmaxf(tm1, __shfl_xor_sync(0xffffffffu, tm1, 1, 4));
        tm1 = fmaxf(tm1, __shfl_xor_sync(0xffffffffu, tm1, 2, 4));
        tm2 = fmaxf(tm2, __shfl_xor_sync(0xffffffffu, tm2, 1, 4));
        tm2 = fmaxf(tm2, __shfl_xor_sync(0xffffffffu, tm2, 2, 4));

        float mn1 = fmaxf(m1, tm1), mn2 = fmaxf(m2, tm2);
        bool dead1 = (mn1 == -INFINITY), dead2 = (mn2 == -INFINITY);
        float f1 = dead1 ? 1.f : __expf(m1 - mn1);
        float f2 = dead2 ? 1.f : __expf(m2 - mn2);
        m1 = mn1; m2 = mn2;

        float rs1 = 0.f, rs2 = 0.f;
        #pragma unroll
        for (int j = 0; j < 16; j++) {
            float p0 = dead1 ? 0.f : __expf(sc[j][0] - mn1);
            float p1 = dead1 ? 0.f : __expf(sc[j][1] - mn1);
            float p2 = dead2 ? 0.f : __expf(sc[j][2] - mn2);
            float p3 = dead2 ? 0.f : __expf(sc[j][3] - mn2);
            sc[j][0] = p0; sc[j][1] = p1; sc[j][2] = p2; sc[j][3] = p3;
            rs1 += p0 + p1; rs2 += p2 + p3;
        }
        rs1 += __shfl_xor_sync(0xffffffffu, rs1, 1, 4);
        rs1 += __shfl_xor_sync(0xffffffffu, rs1, 2, 4);
        rs2 += __shfl_xor_sync(0xffffffffu, rs2, 1, 4);
        rs2 += __shfl_xor_sync(0xffffffffu, rs2, 2, 4);
        l1 = l1 * f1 + rs1;
        l2 = l2 * f2 + rs2;

        #pragma unroll
        for (int j = 0; j < 10; j++) {
            oacc[j][0] *= f1; oacc[j][1] *= f1;
            oacc[j][2] *= f2; oacc[j][3] *= f2;
        }

        // ---- O += P V : P split in regs, V via ldmatrix.trans ----
        #pragma unroll
        for (int kc = 0; kc < 8; kc++) {
            uint32_t pah[4], pal[4];
            splitpack(sc[2 * kc][0],     sc[2 * kc][1],     pah[0], pal[0]);
            splitpack(sc[2 * kc][2],     sc[2 * kc][3],     pah[1], pal[1]);
            splitpack(sc[2 * kc + 1][0], sc[2 * kc + 1][1], pah[2], pal[2]);
            splitpack(sc[2 * kc + 1][2], sc[2 * kc + 1][3], pah[3], pal[3]);
            #pragma unroll
            for (int dv = 0; dv < 5; dv++) {
                uint32_t vh[4], vl[4];
                uint32_t voff = (uint32_t)((kc * 16 + (lane & 15)) * QSTR
                                 + dv * 16 + ((lane >> 4) << 3)) * 2;
                ldsm4t(vh, sVh + voff);
                ldsm4t(vl, sVl + voff);
                mma16816(oacc[2 * dv],     pah, vh);
                mma16816(oacc[2 * dv],     pah, vl);
                mma16816(oacc[2 * dv],     pal, vh);
                mma16816(oacc[2 * dv + 1], pah, vh + 2);
                mma16816(oacc[2 * dv + 1], pah, vl + 2);
                mma16816(oacc[2 * dv + 1], pal, vh + 2);
            }
        }
    }

    // ---- finalize: O/l, split to bf16 hi/lo, write ----
    float inv1 = (l1 > 0.f) ? 1.f / l1 : 0.f;
    float inv2 = (l2 > 0.f) ? 1.f / l2 : 0.f;
    #pragma unroll
    for (int j = 0; j < 10; j++) {
        int dcol = h * HD + j * 8 + ((lane & 3) << 1);
        size_t o1 = (size_t)gr1 * HID + dcol;
        size_t o2 = (size_t)(gr1 + 8) * HID + dcol;
        uint32_t ph, pl;
        splitpack(oacc[j][0] * inv1, oacc[j][1] * inv1, ph, pl);
        *(uint32_t*)(Oh_ + o1) = ph;
        *(uint32_t*)(Ol_ + o1) = pl;
        splitpack(oacc[j][2] * inv2, oacc[j][3] * inv2, ph, pl);
        *(uint32_t*)(Oh_ + o2) = ph;
        *(uint32_t*)(Ol_ + o2) = pl;
    }
}

// ---------------- launch ----------------------------------------------------
extern "C" void kernel_launch(void* const* d_in, const int* in_sizes, int n_in,
                              void* d_out, int out_size)
{
    const float* hidden = (const float*)d_in[0];
    const float* cosp   = (const float*)d_in[1];
    const float* sinp   = (const float*)d_in[2];
    const float* qkv_w  = (const float*)d_in[3];
    const float* qkv_b  = (const float*)d_in[4];
    const float* proj_w = (const float*)d_in[5];
    const float* proj_b = (const float*)d_in[6];
    const int*   cu     = (const int*)d_in[7];
    const int    nseg   = in_sizes[7] - 1;
    float* out = (float*)d_out;

    float* qkv;
    cudaGetSymbolAddress((void**)&qkv, g_qkv);
    __nv_bfloat16 *hh, *hl, *wh, *wl, *ph, *pl;
    __nv_bfloat16 *qh, *ql, *kh, *kl, *vh, *vl, *ah, *al;
    cudaGetSymbolAddress((void**)&hh, g_hh);
    cudaGetSymbolAddress((void**)&hl, g_hl);
    cudaGetSymbolAddress((void**)&wh, g_wh);
    cudaGetSymbolAddress((void**)&wl, g_wl);
    cudaGetSymbolAddress((void**)&ph, g_ph);
    cudaGetSymbolAddress((void**)&pl, g_pl);
    cudaGetSymbolAddress((void**)&qh, g_qh);
    cudaGetSymbolAddress((void**)&ql, g_ql);
    cudaGetSymbolAddress((void**)&kh, g_kh);
    cudaGetSymbolAddress((void**)&kl, g_kl);
    cudaGetSymbolAddress((void**)&vh, g_vh);
    cudaGetSymbolAddress((void**)&vl, g_vl);
    cudaGetSymbolAddress((void**)&ah, g_ah);
    cudaGetSymbolAddress((void**)&al, g_al);

    cudaFuncSetAttribute(hmma_gemm_kernel,
                         cudaFuncAttributeMaxDynamicSharedMemorySize, HMMA_SMEM);
    cudaFuncSetAttribute(hmma_attn_kernel,
                         cudaFuncAttributeMaxDynamicSharedMemorySize, ATTN_SMEM);

    // 0) split inputs/weights
    {
        int n1 = SEQ * HID;
        split_kernel<<<(n1 + 255) / 256, 256>>>(hidden, hh, hl, n1);
        int n2 = 3 * HID * HID;
        split_kernel<<<(n2 + 255) / 256, 256>>>(qkv_w, wh, wl, n2);
        int n3 = HID * HID;
        split_kernel<<<(n3 + 255) / 256, 256>>>(proj_w, ph, pl, n3);
    }
    // 1) QKV GEMM (HMMA split-bf16)
    {
        dim3 grid((3 * HID) / 128, SEQ / 128);
        hmma_gemm_kernel<<<grid, 256, HMMA_SMEM>>>(hh, hl, wh, wl,
                                                   qkv_b, qkv, 3 * HID, HID);
    }
    // 2) RoPE + split to head-major bf16
    {
        int total = SEQ * NH * HD;
        rope_split_kernel<<<(total + 255) / 256, 256>>>(cosp, sinp);
    }
    // 3) Attention (HMMA flash, split-bf16)
    {
        dim3 grid(SEQ / 128, NH);
        hmma_attn_kernel<<<grid, 256, ATTN_SMEM>>>(qh, ql, kh, kl, vh, vl,
                                                   cu, nseg, ah, al);
    }
    // 4) Output projection (HMMA split-bf16)
    {
        dim3 grid(HID / 128, SEQ / 128);
        hmma_gemm_kernel<<<grid, 256, HMMA_SMEM>>>(ah, al, ph, pl,
                                                   proj_b, out, HID, HID);
    }
}